// round 14
// baseline (speedup 1.0000x reference)
#include <cuda_runtime.h>
#include <cuda_bf16.h>
#include <math.h>
#include <stdint.h>

// Problem constants
#define Bsz 8
#define Ssz 512
#define Dsz 768
#define Hsz 12
#define DHsz 64
#define FFsz 3072
#define MROWS (Bsz*Ssz)   // 4096

// ---------------------------------------------------------------------------
// Scratch (static __device__ arrays; no allocations anywhere)
#define F32_SCR (6*(size_t)MROWS*Dsz + Bsz*Ssz)
static __device__ float g_f32[F32_SCR];
#define BF16_SCR (8*(size_t)MROWS*Dsz + 2*(size_t)MROWS*FFsz + 12*(size_t)Dsz*Dsz + 4*(size_t)Dsz*FFsz)
static __device__ __nv_bfloat16 g_bf16[BF16_SCR];
static __device__ unsigned char g_mask[Bsz*Ssz];
static __device__ int g_mask_is_int;

// ---------------------------------------------------------------------------
__device__ __forceinline__ uint32_t smem_u32(const void* p) {
    uint32_t a;
    asm("{ .reg .u64 t; cvta.to.shared.u64 t, %1; cvt.u32.u64 %0, t; }" : "=r"(a) : "l"(p));
    return a;
}
__device__ __forceinline__ void split2(float v, __nv_bfloat16& h, __nv_bfloat16& l) {
    h = __float2bfloat16(v);
    l = __float2bfloat16(v - __bfloat162float(h));
}
__device__ __forceinline__ void cp_async16(uint32_t saddr, const void* gptr) {
    asm volatile("cp.async.cg.shared.global [%0], [%1], 16;\n" :: "r"(saddr), "l"(gptr));
}
__device__ __forceinline__ void cp_commit() { asm volatile("cp.async.commit_group;\n"); }
__device__ __forceinline__ void cp_wait0() { asm volatile("cp.async.wait_group 0;\n"); }

__device__ __forceinline__ void ldsm_x4(uint32_t* r, uint32_t addr) {
    asm volatile("ldmatrix.sync.aligned.m8n8.x4.shared.b16 {%0,%1,%2,%3}, [%4];"
                 : "=r"(r[0]), "=r"(r[1]), "=r"(r[2]), "=r"(r[3]) : "r"(addr));
}
__device__ __forceinline__ void mma_bf16(float* c, const uint32_t* a, const uint32_t* b) {
    asm volatile(
        "mma.sync.aligned.m16n8k16.row.col.f32.bf16.bf16.f32 "
        "{%0,%1,%2,%3}, {%4,%5,%6,%7}, {%8,%9}, {%0,%1,%2,%3};\n"
        : "+f"(c[0]), "+f"(c[1]), "+f"(c[2]), "+f"(c[3])
        : "r"(a[0]), "r"(a[1]), "r"(a[2]), "r"(a[3]), "r"(b[0]), "r"(b[1]));
}

// ---------------------------------------------------------------------------
// Split-bf16 3-pass GEMM: Y[M,N] = (Ah+Al)[M,K] @ (Bh+Bl)[N,K]^T + bias
// fuse: 0 = f32 out; 1 = relu + split-bf16 out; 2 = +res, f32 out
// CTA 128x128, BK=32, 256 threads (8 warps), warp tile 64x32.
// smem: 2 buffers x (Ah|Al|Bh|Bl), each tile 128 rows x 64B (bf16), XOR-swizzled.
#define G_TILE 8192
#define G_BUF  32768
#define G_SMEM 65536

struct GemmArgs {
    const __nv_bfloat16 *Ah, *Al, *Bh, *Bl;
    const float *bias, *res;
    float* Yf;
    __nv_bfloat16 *Yh, *Yl;
};
struct GemmBatch { GemmArgs a[3]; };

__global__ __launch_bounds__(256) void gemm_bf16x3_kernel(
    GemmBatch gb, int M, int N, int K, int fuse)
{
    const GemmArgs ga = gb.a[blockIdx.z];
    extern __shared__ unsigned char dsm[];
    const uint32_t sbase = smem_u32(dsm);

    const int tid = threadIdx.x, wid = tid >> 5, lane = tid & 31;
    const int gID = lane >> 2, tig = lane & 3;
    const int warp_m = (wid & 1) * 64, warp_n = (wid >> 1) * 32;
    const int m0 = blockIdx.y * 128, n0 = blockIdx.x * 128;

    // per-lane ldmatrix row/half constants
    const int rA  = warp_m + (lane & 15);               // A row (tile-local)
    const int khA = lane >> 4;                          // k-half 0/1
    const int swA = (rA >> 1) & 3;
    const int rB  = warp_n + (lane & 7) + (((lane >> 4) & 1) << 3);
    const int khB = (lane >> 3) & 1;
    const int swB = (rB >> 1) & 3;

    float acc[4][4][4];
    #pragma unroll
    for (int i = 0; i < 4; i++)
        #pragma unroll
        for (int j = 0; j < 4; j++)
            #pragma unroll
            for (int c = 0; c < 4; c++) acc[i][j][c] = 0.0f;

    // stage K-slab kt into buffer buf: 2048 16B-chunks, 8 per thread
    auto stage = [&](int kt, int buf) {
        #pragma unroll
        for (int i = 0; i < 8; i++) {
            const int id  = tid + 256 * i;
            const int arr = id >> 9;            // 0:Ah 1:Al 2:Bh 3:Bl
            const int row = (id >> 2) & 127;
            const int c   = id & 3;
            const __nv_bfloat16* g =
                (arr == 0) ? ga.Ah : (arr == 1) ? ga.Al : (arr == 2) ? ga.Bh : ga.Bl;
            const int grow = ((arr < 2) ? m0 : n0) + row;
            const uint32_t sw = (uint32_t)(c ^ ((row >> 1) & 3));
            cp_async16(sbase + (uint32_t)buf * G_BUF + (uint32_t)arr * G_TILE
                           + (uint32_t)row * 64 + sw * 16,
                       g + (size_t)grow * K + kt * 32 + c * 8);
        }
    };

    const int nk = K / 32;
    stage(0, 0);
    cp_commit();

    for (int kt = 0; kt < nk; kt++) {
        const int buf = kt & 1;
        cp_wait0();
        __syncthreads();
        if (kt + 1 < nk) { stage(kt + 1, buf ^ 1); cp_commit(); }

        const uint32_t bb = sbase + (uint32_t)buf * G_BUF;
        #pragma unroll
        for (int s = 0; s < 2; s++) {
            const uint32_t cB = (uint32_t)(((2 * s + khB) ^ swB) * 16);
            uint32_t Bhf[2][4], Blf[2][4];
            #pragma unroll
            for (int p = 0; p < 2; p++) {
                const uint32_t baddr = bb + (uint32_t)(rB + 16 * p) * 64 + cB;
                ldsm_x4(Bhf[p], baddr + 2u * G_TILE);
                ldsm_x4(Blf[p], baddr + 3u * G_TILE);
            }
            const uint32_t cA = (uint32_t)(((2 * s + khA) ^ swA) * 16);
            #pragma unroll
            for (int mt = 0; mt < 4; mt++) {
                const uint32_t aaddr = bb + (uint32_t)(rA + 16 * mt) * 64 + cA;
                uint32_t Ahf[4], Alf[4];
                ldsm_x4(Ahf, aaddr);
                ldsm_x4(Alf, aaddr + G_TILE);
                #pragma unroll
                for (int nt = 0; nt < 4; nt++) {
                    const uint32_t* b2h = &Bhf[nt >> 1][(nt & 1) * 2];
                    const uint32_t* b2l = &Blf[nt >> 1][(nt & 1) * 2];
                    mma_bf16(acc[mt][nt], Ahf, b2h);
                    mma_bf16(acc[mt][nt], Ahf, b2l);
                    mma_bf16(acc[mt][nt], Alf, b2h);
                }
            }
        }
    }

    // epilogue (register accumulators; D layout: c0,c1 row m; c2,c3 row m+8)
    #pragma unroll
    for (int mt = 0; mt < 4; mt++) {
        const int m = m0 + warp_m + mt * 16 + gID;
        #pragma unroll
        for (int nt = 0; nt < 4; nt++) {
            const int n = n0 + warp_n + nt * 8 + 2 * tig;
            const float* c = acc[mt][nt];
            const float bv0 = ga.bias[n], bv1 = ga.bias[n + 1];
            float v00 = c[0] + bv0, v01 = c[1] + bv1;
            float v10 = c[2] + bv0, v11 = c[3] + bv1;
            if (fuse == 1) {
                v00 = fmaxf(v00, 0.0f); v01 = fmaxf(v01, 0.0f);
                v10 = fmaxf(v10, 0.0f); v11 = fmaxf(v11, 0.0f);
                __nv_bfloat16 h0, l0, h1, l1;
                split2(v00, h0, l0); split2(v01, h1, l1);
                *(__nv_bfloat162*)(ga.Yh + (size_t)m * N + n) = __nv_bfloat162(h0, h1);
                *(__nv_bfloat162*)(ga.Yl + (size_t)m * N + n) = __nv_bfloat162(l0, l1);
                split2(v10, h0, l0); split2(v11, h1, l1);
                *(__nv_bfloat162*)(ga.Yh + (size_t)(m + 8) * N + n) = __nv_bfloat162(h0, h1);
                *(__nv_bfloat162*)(ga.Yl + (size_t)(m + 8) * N + n) = __nv_bfloat162(l0, l1);
            } else {
                if (fuse == 2) {
                    float2 r0 = *(const float2*)(ga.res + (size_t)m * N + n);
                    float2 r1 = *(const float2*)(ga.res + (size_t)(m + 8) * N + n);
                    v00 += r0.x; v01 += r0.y; v10 += r1.x; v11 += r1.y;
                }
                *(float2*)(ga.Yf + (size_t)m * N + n)       = make_float2(v00, v01);
                *(float2*)(ga.Yf + (size_t)(m + 8) * N + n) = make_float2(v10, v11);
            }
        }
    }
}

// ---------------------------------------------------------------------------
// Weight prep: W [K,N] f32 -> WT hi/lo [N,K] bf16 (32x32 smem tile transpose)
__global__ __launch_bounds__(256) void transpose_split_kernel(
    const float* __restrict__ W, __nv_bfloat16* __restrict__ Th,
    __nv_bfloat16* __restrict__ Tl, int K, int N)
{
    __shared__ float t[32][33];
    const int tx = threadIdx.x, ty = threadIdx.y;
    const int n0 = blockIdx.x * 32, k0 = blockIdx.y * 32;
    #pragma unroll
    for (int j = ty; j < 32; j += 8)
        t[j][tx] = W[(size_t)(k0 + j) * N + n0 + tx];
    __syncthreads();
    #pragma unroll
    for (int j = ty; j < 32; j += 8) {
        const int nn = n0 + j;
        float v = t[tx][j];
        __nv_bfloat16 h, l; split2(v, h, l);
        Th[(size_t)nn * K + k0 + tx] = h;
        Tl[(size_t)nn * K + k0 + tx] = l;
    }
}

// Elementwise split: f32 -> bf16 hi/lo
__global__ void split_kernel(const float* __restrict__ X,
                             __nv_bfloat16* __restrict__ Xh,
                             __nv_bfloat16* __restrict__ Xl, int n)
{
    int i = blockIdx.x * 256 + threadIdx.x;
    if (i < n) {
        __nv_bfloat16 h, l; split2(X[i], h, l);
        Xh[i] = h; Xl[i] = l;
    }
}

// ---------------------------------------------------------------------------
// LayerNorm over last dim (768), one block per row; split-bf16 output.
__global__ __launch_bounds__(256) void layernorm_split_kernel(
    const float* __restrict__ X, const float* __restrict__ g,
    const float* __restrict__ be, __nv_bfloat16* __restrict__ Yh,
    __nv_bfloat16* __restrict__ Yl)
{
    __shared__ float red[256];
    __shared__ float s_mean, s_inv;
    const int row = blockIdx.x, tid = threadIdx.x;
    const float* x = X + (size_t)row * Dsz;

    float s = 0.0f;
    for (int i = tid; i < Dsz; i += 256) s += x[i];
    red[tid] = s; __syncthreads();
    for (int o = 128; o > 0; o >>= 1) { if (tid < o) red[tid] += red[tid + o]; __syncthreads(); }
    if (tid == 0) s_mean = red[0] * (1.0f / Dsz);
    __syncthreads();
    const float m = s_mean;

    float v = 0.0f;
    for (int i = tid; i < Dsz; i += 256) { float d = x[i] - m; v += d * d; }
    red[tid] = v; __syncthreads();
    for (int o = 128; o > 0; o >>= 1) { if (tid < o) red[tid] += red[tid + o]; __syncthreads(); }
    if (tid == 0) s_inv = rsqrtf(red[0] * (1.0f / Dsz) + 1e-5f);
    __syncthreads();
    const float inv = s_inv;

    for (int i = tid; i < Dsz; i += 256) {
        float y = (x[i] - m) * inv * g[i] + be[i];
        __nv_bfloat16 h, l; split2(y, h, l);
        Yh[(size_t)row * Dsz + i] = h;
        Yl[(size_t)row * Dsz + i] = l;
    }
}

// ---------------------------------------------------------------------------
// Neighbor affinity (f32 qn/kn)
__global__ __launch_bounds__(128) void affinity_kernel(
    const float* __restrict__ qn, const float* __restrict__ kn,
    const float* __restrict__ prev, const int* __restrict__ lidx,
    float* __restrict__ a_out)
{
    const int t = blockIdx.x, b = blockIdx.y, tid = threadIdx.x;
    const float* q0 = qn + ((size_t)b * Ssz + t) * Dsz;
    const float* q1 = q0 + Dsz;
    const float* k0 = kn + ((size_t)b * Ssz + t) * Dsz;
    const float* k1 = k0 + Dsz;
    float sf = 0.0f, sb = 0.0f;
    for (int i = tid; i < Dsz; i += 128) { sf += q0[i] * k1[i]; sb += q1[i] * k0[i]; }
    __shared__ float rf[128], rb[128];
    rf[tid] = sf; rb[tid] = sb; __syncthreads();
    for (int o = 64; o > 0; o >>= 1) {
        if (tid < o) { rf[tid] += rf[tid + o]; rb[tid] += rb[tid + o]; }
        __syncthreads();
    }
    if (tid == 0) {
        float f = rf[0] * (1.0f / 64.0f), bw = rb[0] * (1.0f / 64.0f);
        float ah = 0.5f * (1.0f / (1.0f + expf(-f)) + 1.0f / (1.0f + expf(-bw)));
        float a;
        if (*lidx == 0) a = ah;
        else { float p = prev[(size_t)b * (Ssz - 1) + t]; a = p + (1.0f - p) * ah; }
        a_out[(size_t)b * (Ssz - 1) + t] = a;
    }
}

// L[b,0]=0; L[b,k]=sum_{t<k} log(a[b,t])
__global__ void scan_kernel(const float* __restrict__ a, float* __restrict__ Lout)
{
    const int b = blockIdx.x;
    if (threadIdx.x == 0) {
        float acc = 0.0f;
        Lout[(size_t)b * Ssz] = 0.0f;
        for (int t = 0; t < Ssz - 1; t++) {
            acc += logf(a[(size_t)b * (Ssz - 1) + t]);
            Lout[(size_t)b * Ssz + t + 1] = acc;
        }
    }
}

// ---------------------------------------------------------------------------
// Mask dtype handling
__global__ void mask_detect_kernel(const unsigned char* __restrict__ m)
{
    if (threadIdx.x == 0)
        g_mask_is_int = (m[1] == 0 && m[2] == 0 && m[3] == 0) ? 1 : 0;
}
__global__ void mask_norm_kernel(const void* __restrict__ m)
{
    int i = blockIdx.x * 256 + threadIdx.x;
    if (i < Bsz * Ssz) {
        int v = g_mask_is_int ? ((const int*)m)[i] : (int)((const unsigned char*)m)[i];
        g_mask[i] = v ? 1 : 0;
    }
}

// ---------------------------------------------------------------------------
// Fused attention; ctx written as split-bf16 (feeds Wo GEMM)
#define ATT_SC 0
#define ATT_QS 16512
#define ATT_KT 18592
#define ATT_LS 26912
#define ATT_MS 27424
#define ATT_SMEM_BYTES ((ATT_MS + 128) * 4)

__global__ __launch_bounds__(256) void attn_fused_kernel(
    const float* __restrict__ gq, const float* __restrict__ gk,
    const float* __restrict__ gv, const float* __restrict__ Lg,
    float* __restrict__ attnh,
    __nv_bfloat16* __restrict__ ctxh, __nv_bfloat16* __restrict__ ctxl)
{
    extern __shared__ float sm[];
    float* Sc = sm + ATT_SC;
    float* qs = sm + ATT_QS;
    float* kt = sm + ATT_KT;
    float* Ls = sm + ATT_LS;
    unsigned char* ms = (unsigned char*)(sm + ATT_MS);

    const int tid = threadIdx.x;
    const int bh = blockIdx.y, b = bh / Hsz, h = bh % Hsz;
    const int q0 = blockIdx.x * 32;

    for (int i = tid; i < Ssz; i += 256) {
        Ls[i] = Lg[(size_t)b * Ssz + i];
        ms[i] = g_mask[(size_t)b * Ssz + i];
    }
    {
        int r = tid >> 3, d8 = (tid & 7) << 3;
        const float* src = gq + ((size_t)b * Ssz + q0 + r) * Dsz + h * DHsz + d8;
        float* dst = qs + r * 65 + d8;
        #pragma unroll
        for (int u = 0; u < 8; u++) dst[u] = src[u];
    }
    __syncthreads();

    const int qg = tid >> 5;
    const int kg = tid & 31;

    for (int t = 0; t < 4; t++) {
        const int k0 = t * 128;
        {
            int krow = tid >> 1, dd = (tid & 1) << 5;
            const float* src = gk + ((size_t)b * Ssz + k0 + krow) * Dsz + h * DHsz + dd;
            float* dst = kt + krow * 65 + dd;
            #pragma unroll
            for (int u = 0; u < 32; u++) dst[u] = src[u];
        }
        __syncthreads();
        float acc[4][4] = {};
        #pragma unroll 4
        for (int dh = 0; dh < DHsz; dh++) {
            float qv[4], kv[4];
            #pragma unroll
            for (int i = 0; i < 4; i++) qv[i] = qs[(qg * 4 + i) * 65 + dh];
            #pragma unroll
            for (int j = 0; j < 4; j++) kv[j] = kt[(kg + 32 * j) * 65 + dh];
            #pragma unroll
            for (int i = 0; i < 4; i++)
                #pragma unroll
                for (int j = 0; j < 4; j++) acc[i][j] += qv[i] * kv[j];
        }
        #pragma unroll
        for (int i = 0; i < 4; i++)
            #pragma unroll
            for (int j = 0; j < 4; j++) {
                int kgl = k0 + kg + 32 * j;
                float vv = acc[i][j] * 0.125f;
                if (!ms[kgl]) vv = -1e9f;
                Sc[(qg * 4 + i) * 516 + kgl] = vv;
            }
        __syncthreads();
    }

    {
        const int row = tid >> 3, l8 = tid & 7;
        float* sr = Sc + row * 516;
        float mx = -1e30f;
        #pragma unroll 8
        for (int i = 0; i < 64; i++) mx = fmaxf(mx, sr[l8 + 8 * i]);
        for (int o = 1; o < 8; o <<= 1) mx = fmaxf(mx, __shfl_xor_sync(0xffffffffu, mx, o));
        float sum = 0.0f;
        #pragma unroll 8
        for (int i = 0; i < 64; i++) {
            int k = l8 + 8 * i;
            float e = __expf(sr[k] - mx);
            sr[k] = e; sum += e;
        }
        for (int o = 1; o < 8; o <<= 1) sum += __shfl_xor_sync(0xffffffffu, sum, o);
        const float inv = 1.0f / sum;
        const int qi = q0 + row;
        const float Lq = Ls[qi];
        #pragma unroll 8
        for (int i = 0; i < 64; i++) {
            int k = l8 + 8 * i;
            float Lk = Ls[k];
            float c = (qi >= k) ? __expf(Lq - Lk) : __expf(Lk - Lq);
            sr[k] = sr[k] * inv * c;
        }
    }
    __syncthreads();

    {
        float* dst = attnh + (size_t)bh * Ssz * Ssz + (size_t)q0 * Ssz;
        for (int idx = tid; idx < 32 * 512; idx += 256) {
            int r = idx >> 9, k = idx & 511;
            dst[(size_t)r * Ssz + k] = Sc[r * 516 + k];
        }
    }

    float oacc[2][4] = {};
    const int r0 = (tid >> 4) << 1;
    const int c0 = (tid & 15) << 2;
    for (int t = 0; t < 4; t++) {
        const int k0 = t * 128;
        __syncthreads();
        {
            int krow = tid >> 1, dd = (tid & 1) << 5;
            const float* src = gv + ((size_t)b * Ssz + k0 + krow) * Dsz + h * DHsz + dd;
            float* dst = kt + krow * 65 + dd;
            #pragma unroll
            for (int u = 0; u < 32; u++) dst[u] = src[u];
        }
        __syncthreads();
        #pragma unroll 4
        for (int kk = 0; kk < 128; kk++) {
            float a0 = Sc[r0 * 516 + k0 + kk];
            float a1 = Sc[(r0 + 1) * 516 + k0 + kk];
            const float* vr = kt + kk * 65 + c0;
            #pragma unroll
            for (int j = 0; j < 4; j++) { float bv = vr[j]; oacc[0][j] += a0 * bv; oacc[1][j] += a1 * bv; }
        }
    }
    #pragma unroll
    for (int rr = 0; rr < 2; rr++) {
        const size_t base = ((size_t)b * Ssz + q0 + r0 + rr) * Dsz + h * DHsz + c0;
        __nv_bfloat16 h0, l0, h1, l1, h2, l2, h3, l3;
        split2(oacc[rr][0], h0, l0); split2(oacc[rr][1], h1, l1);
        split2(oacc[rr][2], h2, l2); split2(oacc[rr][3], h3, l3);
        *(__nv_bfloat162*)(ctxh + base)     = __nv_bfloat162(h0, h1);
        *(__nv_bfloat162*)(ctxh + base + 2) = __nv_bfloat162(h2, h3);
        *(__nv_bfloat162*)(ctxl + base)     = __nv_bfloat162(l0, l1);
        *(__nv_bfloat162*)(ctxl + base + 2) = __nv_bfloat162(l2, l3);
    }
}

// ---------------------------------------------------------------------------
extern "C" void kernel_launch(void* const* d_in, const int* in_sizes, int n_in,
                              void* d_out, int out_size)
{
    (void)in_sizes; (void)n_in; (void)out_size;
    const float* x    = (const float*)d_in[0];
    const void*  mask = d_in[1];
    const float* prev = (const float*)d_in[2];
    const float* Wqn  = (const float*)d_in[3];  const float* bqn = (const float*)d_in[4];
    const float* Wkn  = (const float*)d_in[5];  const float* bkn = (const float*)d_in[6];
    const float* Wq   = (const float*)d_in[7];  const float* bq  = (const float*)d_in[8];
    const float* Wk   = (const float*)d_in[9];  const float* bk  = (const float*)d_in[10];
    const float* Wv   = (const float*)d_in[11]; const float* bv  = (const float*)d_in[12];
    const float* Wo   = (const float*)d_in[13]; const float* bo  = (const float*)d_in[14];
    const float* W1   = (const float*)d_in[15]; const float* b1  = (const float*)d_in[16];
    const float* W2   = (const float*)d_in[17]; const float* b2  = (const float*)d_in[18];
    const float* g1   = (const float*)d_in[19]; const float* be1 = (const float*)d_in[20];
    const float* g2   = (const float*)d_in[21]; const float* be2 = (const float*)d_in[22];
    const int*   lidx = (const int*)d_in[23];

    float* out_p   = (float*)d_out;
    float* a_p     = out_p + (size_t)MROWS * Dsz;
    float* attnh_p = a_p + (size_t)Bsz * (Ssz - 1);

    // carve f32 scratch
    void* basep = nullptr;
    cudaGetSymbolAddress(&basep, g_f32);
    float* qn = (float*)basep;
    float* kn = qn + (size_t)MROWS * Dsz;
    float* qb = kn + (size_t)MROWS * Dsz;
    float* kb = qb + (size_t)MROWS * Dsz;
    float* vb = kb + (size_t)MROWS * Dsz;
    float* x1 = vb + (size_t)MROWS * Dsz;
    float* Lb = x1 + (size_t)MROWS * Dsz;

    // carve bf16 scratch
    cudaGetSymbolAddress(&basep, g_bf16);
    __nv_bfloat16* p = (__nv_bfloat16*)basep;
    const size_t MD = (size_t)MROWS * Dsz, MF = (size_t)MROWS * FFsz;
    const size_t DD = (size_t)Dsz * Dsz, DF = (size_t)Dsz * FFsz;
    __nv_bfloat16 *xrh = p,   *xrl = p + MD;      p += 2 * MD;
    __nv_bfloat16 *xnh = p,   *xnl = p + MD;      p += 2 * MD;
    __nv_bfloat16 *cxh = p,   *cxl = p + MD;      p += 2 * MD;
    __nv_bfloat16 *x2h = p,   *x2l = p + MD;      p += 2 * MD;
    __nv_bfloat16 *hih = p,   *hil = p + MF;      p += 2 * MF;
    __nv_bfloat16 *WqnTh = p, *WqnTl = p + DD;    p += 2 * DD;
    __nv_bfloat16 *WknTh = p, *WknTl = p + DD;    p += 2 * DD;
    __nv_bfloat16 *WqTh  = p, *WqTl  = p + DD;    p += 2 * DD;
    __nv_bfloat16 *WkTh  = p, *WkTl  = p + DD;    p += 2 * DD;
    __nv_bfloat16 *WvTh  = p, *WvTl  = p + DD;    p += 2 * DD;
    __nv_bfloat16 *WoTh  = p, *WoTl  = p + DD;    p += 2 * DD;
    __nv_bfloat16 *W1Th  = p, *W1Tl  = p + DF;    p += 2 * DF;
    __nv_bfloat16 *W2Th  = p, *W2Tl  = p + DF;

    cudaFuncSetAttribute(attn_fused_kernel,
                         cudaFuncAttributeMaxDynamicSharedMemorySize, ATT_SMEM_BYTES);
    cudaFuncSetAttribute(gemm_bf16x3_kernel,
                         cudaFuncAttributeMaxDynamicSharedMemorySize, G_SMEM);

    const dim3 tb(32, 8);
    const dim3 tD(Dsz / 32, Dsz / 32);
    const dim3 t1(FFsz / 32, Dsz / 32);
    const dim3 t2(Dsz / 32, FFsz / 32);

    // 1-3: QKV weights  4: LN1  5: split x  6: QKV GEMM (profiled slot)
    transpose_split_kernel<<<tD, tb>>>(Wq, WqTh, WqTl, Dsz, Dsz);
    transpose_split_kernel<<<tD, tb>>>(Wk, WkTh, WkTl, Dsz, Dsz);
    transpose_split_kernel<<<tD, tb>>>(Wv, WvTh, WvTl, Dsz, Dsz);
    layernorm_split_kernel<<<MROWS, 256>>>(x, g1, be1, xnh, xnl);
    split_kernel<<<(int)((MD + 255) / 256), 256>>>(x, xrh, xrl, (int)MD);
    {
        GemmBatch gbat;
        gbat.a[0] = { xnh, xnl, WqTh, WqTl, bq, nullptr, qb, nullptr, nullptr };
        gbat.a[1] = { xnh, xnl, WkTh, WkTl, bk, nullptr, kb, nullptr, nullptr };
        gbat.a[2] = { xnh, xnl, WvTh, WvTl, bv, nullptr, vb, nullptr, nullptr };
        gemm_bf16x3_kernel<<<dim3(Dsz / 128, MROWS / 128, 3), 256, G_SMEM>>>(
            gbat, MROWS, Dsz, Dsz, 0);
    }
    // rest of weight prep
    transpose_split_kernel<<<tD, tb>>>(Wqn, WqnTh, WqnTl, Dsz, Dsz);
    transpose_split_kernel<<<tD, tb>>>(Wkn, WknTh, WknTl, Dsz, Dsz);
    transpose_split_kernel<<<tD, tb>>>(Wo, WoTh, WoTl, Dsz, Dsz);
    transpose_split_kernel<<<t1, tb>>>(W1, W1Th, W1Tl, Dsz, FFsz);
    transpose_split_kernel<<<t2, tb>>>(W2, W2Th, W2Tl, FFsz, Dsz);
    mask_detect_kernel<<<1, 32>>>((const unsigned char*)mask);
    mask_norm_kernel<<<16, 256>>>(mask);

    // affinity path
    {
        GemmBatch gbat;
        gbat.a[0] = { xrh, xrl, WqnTh, WqnTl, bqn, nullptr, qn, nullptr, nullptr };
        gbat.a[1] = { xrh, xrl, WknTh, WknTl, bkn, nullptr, kn, nullptr, nullptr };
        gbat.a[2] = gbat.a[0];
        gemm_bf16x3_kernel<<<dim3(Dsz / 128, MROWS / 128, 2), 256, G_SMEM>>>(
            gbat, MROWS, Dsz, Dsz, 0);
    }
    affinity_kernel<<<dim3(Ssz - 1, Bsz), 128>>>(qn, kn, prev, lidx, a_p);
    scan_kernel<<<Bsz, 32>>>(a_p, Lb);

    // attention
    attn_fused_kernel<<<dim3(Ssz / 32, Bsz * Hsz), 256, ATT_SMEM_BYTES>>>(
        qb, kb, vb, Lb, attnh_p, cxh, cxl);

    // output proj + residual -> x1
    {
        GemmBatch gbat;
        gbat.a[0] = { cxh, cxl, WoTh, WoTl, bo, x, x1, nullptr, nullptr };
        gbat.a[1] = gbat.a[0]; gbat.a[2] = gbat.a[0];
        gemm_bf16x3_kernel<<<dim3(Dsz / 128, MROWS / 128, 1), 256, G_SMEM>>>(
            gbat, MROWS, Dsz, Dsz, 2);
    }
    layernorm_split_kernel<<<MROWS, 256>>>(x1, g2, be2, x2h, x2l);
    // FFN1: relu + split output
    {
        GemmBatch gbat;
        gbat.a[0] = { x2h, x2l, W1Th, W1Tl, b1, nullptr, nullptr, hih, hil };
        gbat.a[1] = gbat.a[0]; gbat.a[2] = gbat.a[0];
        gemm_bf16x3_kernel<<<dim3(FFsz / 128, MROWS / 128, 1), 256, G_SMEM>>>(
            gbat, MROWS, FFsz, Dsz, 1);
    }
    // FFN2: + residual x1 -> out
    {
        GemmBatch gbat;
        gbat.a[0] = { hih, hil, W2Th, W2Tl, b2, x1, out_p, nullptr, nullptr };
        gbat.a[1] = gbat.a[0]; gbat.a[2] = gbat.a[0];
        gemm_bf16x3_kernel<<<dim3(Dsz / 128, MROWS / 128, 1), 256, G_SMEM>>>(
            gbat, MROWS, Dsz, FFsz, 2);
    }
}